// round 13
// baseline (speedup 1.0000x reference)
#include <cuda_runtime.h>

// Fixed problem shapes
#define DIMD 272
#define NC   19
#define WN   24                  // padded W cols = 3 n-tiles of 8
#define NPAIR 10
#define ZROWF 32                 // Z row stride floats = 128 B
#define NROWS 65536
#define NISEG 4096
#define THREADS 128
#define WARPS 4
#define WROWS 16                 // rows per warp
#define TB_ROWS (WARPS * WROWS)          // 64 rows per proj block
#define PROJ_BLOCKS (NROWS / TB_ROWS)    // 1024
#define NSTAGE 17                // 272 cols = 17 chunks of 16
#define XST 80                   // stage row stride bytes (64 data + 16 pad)
#define DEPTH 3
#define WSTAGE_BYTES (WROWS * XST)       // 1280 per warp per stage
#define WRING_BYTES (DEPTH * WSTAGE_BYTES)  // 3840 per warp
#define PPT 16                   // points/thread in bounds part

typedef unsigned long long ull;

__device__ float g_Z[(size_t)NROWS * ZROWF];    // 8 MB, 128B rows
__device__ int   g_off[NISEG + 1];

__device__ __forceinline__ ull pack2(float lo, float hi) {
    ull r; asm("mov.b64 %0, {%1, %2};" : "=l"(r) : "f"(lo), "f"(hi)); return r;
}
__device__ __forceinline__ void unpack2(ull v, float& lo, float& hi) {
    asm("mov.b64 {%0, %1}, %2;" : "=f"(lo), "=f"(hi) : "l"(v));
}
__device__ __forceinline__ void add2(ull& d, ull a) {
    asm("add.rn.f32x2 %0, %0, %1;" : "+l"(d) : "l"(a));
}
__device__ __forceinline__ unsigned f2tf32(float f) {
    unsigned u; asm("cvt.rna.tf32.f32 %0, %1;" : "=r"(u) : "f"(f)); return u;
}
__device__ __forceinline__ void mma_tf32(float* d, unsigned a0, unsigned a1,
                                         unsigned a2, unsigned a3,
                                         unsigned b0, unsigned b1) {
    asm volatile(
        "mma.sync.aligned.m16n8k8.row.col.f32.tf32.tf32.f32 "
        "{%0,%1,%2,%3}, {%4,%5,%6,%7}, {%8,%9}, {%0,%1,%2,%3};"
        : "+f"(d[0]), "+f"(d[1]), "+f"(d[2]), "+f"(d[3])
        : "r"(a0), "r"(a1), "r"(a2), "r"(a3), "r"(b0), "r"(b1));
}
__device__ __forceinline__ void cpasync16(unsigned smem, const void* g) {
    asm volatile("cp.async.cg.shared.global [%0], [%1], 16;"
                 :: "r"(smem), "l"(g));
}
__device__ __forceinline__ void cpcommit() {
    asm volatile("cp.async.commit_group;");
}
__device__ __forceinline__ void cpwait2() {
    asm volatile("cp.async.wait_group 2;");
}

// ---------------------------------------------------------------------------
// Fat kernel: blocks [0, PROJ_BLOCKS) compute Z = X@W with tf32 mma.sync fed
// by WARP-AUTONOMOUS cp.async rings (no block barriers in the mainloop —
// producer warp == consumer warp, synchronized by wait_group + syncwarp).
// Remaining blocks compute segment boundary offsets.
// ---------------------------------------------------------------------------
__global__ __launch_bounds__(THREADS)
void fat_kernel(const float* __restrict__ X, const float* __restrict__ W,
                const int* __restrict__ segs, int P) {
    if (blockIdx.x < PROJ_BLOCKS) {
        __shared__ __align__(16) unsigned ws[DIMD * WN];        // 26112 B
        __shared__ __align__(16) char xs[WARPS * WRING_BYTES];  // 15360 B

        const int t = threadIdx.x;
        const int warp = t >> 5;
        const int lane = t & 31;
        const int row0 = blockIdx.x * TB_ROWS + warp * WROWS;
        const char* gX = (const char*)(X + (size_t)row0 * DIMD);
        const unsigned ring = (unsigned)__cvta_generic_to_shared(xs)
                            + (unsigned)(warp * WRING_BYTES);

        // Warp-local stage issue: 16 rows x 64 B = 64x16B chunks, 2/lane.
        // (1088 = 17*64: every 64-B chunk is 64-B aligned in gmem.)
        auto issue_stage = [&](int s) {
            unsigned sb = ring + (unsigned)((s % DEPTH) * WSTAGE_BYTES);
            const char* gbase = gX + (size_t)s * 64;
#pragma unroll
            for (int k = 0; k < 2; k++) {
                int i = lane + k * 32;          // 0..63
                int r = i >> 2;
                int c = i & 3;
                cpasync16(sb + (unsigned)(r * XST + c * 16),
                          gbase + (size_t)r * (DIMD * 4) + c * 16);
            }
        };

        issue_stage(0); cpcommit();
        issue_stage(1); cpcommit();
        issue_stage(2); cpcommit();

        // Stage W -> tf32 in shared while cp.asyncs fly
        for (int i = t; i < DIMD * WN; i += THREADS) {
            int dd = i / WN, c = i - dd * WN;
            float v = (c < NC) ? W[dd * NC + c] : 0.f;
            ws[i] = f2tf32(v);
        }
        __syncthreads();          // only block barrier: ws visible

        const int qrow = lane >> 2;           // 0..7
        const int qcol = lane & 3;            // 0..3

        float d[3][4];
#pragma unroll
        for (int n = 0; n < 3; n++)
#pragma unroll
            for (int q = 0; q < 4; q++) d[n][q] = 0.f;

        for (int s = 0; s < NSTAGE; s++) {
            cpwait2();            // this lane's stage-s copies done
            __syncwarp();         // whole warp's copies done

            const char* sbase = xs + warp * WRING_BYTES
                              + (s % DEPTH) * WSTAGE_BYTES;
            // bank = (20r + qcol + co) mod 32: all 32 lanes distinct.
            const float* ar0 = (const float*)(sbase + qrow * XST) + qcol;
            const float* ar1 = (const float*)(sbase + (qrow + 8) * XST) + qcol;

#pragma unroll
            for (int ks = 0; ks < 2; ks++) {
                const int co = ks * 8;
                unsigned a0 = f2tf32(ar0[co]);
                unsigned a1 = f2tf32(ar1[co]);
                unsigned a2 = f2tf32(ar0[co + 4]);
                unsigned a3 = f2tf32(ar1[co + 4]);

                const int kc = s * 16 + co;
                const unsigned* wb = ws + (kc + qcol) * WN + qrow;
#pragma unroll
                for (int n = 0; n < 3; n++) {
                    unsigned b0 = wb[n * 8];
                    unsigned b1 = wb[n * 8 + 4 * WN];
                    mma_tf32(d[n], a0, a1, a2, a3, b0, b1);
                }
            }

            __syncwarp();         // all lanes done reading buffer (s%DEPTH)
            if (s + 3 < NSTAGE) issue_stage(s + 3);
            cpcommit();           // unconditional: uniform group count
        }

        // Epilogue: d[n][0,1] -> row qrow cols n*8+2*qcol ; d[n][2,3] -> +8
        const int r0 = row0 + qrow;
        const int r1 = r0 + 8;
#pragma unroll
        for (int n = 0; n < 3; n++) {
            int c = n * 8 + qcol * 2;
            *(float2*)&g_Z[(size_t)r0 * ZROWF + c] =
                make_float2(d[n][0], d[n][1]);
            *(float2*)&g_Z[(size_t)r1 * ZROWF + c] =
                make_float2(d[n][2], d[n][3]);
        }
    } else {
        // ----------------- segment bounds part -----------------
        const int base = (blockIdx.x - PROJ_BLOCKS) * (THREADS * PPT)
                       + threadIdx.x * PPT;
        if (base >= P) return;
        int vv[PPT];
        const int4* s4 = (const int4*)(segs + base);
#pragma unroll
        for (int q = 0; q < PPT / 4; q++) {
            int4 v = __ldg(s4 + q);
            vv[q*4+0] = v.x; vv[q*4+1] = v.y; vv[q*4+2] = v.z; vv[q*4+3] = v.w;
        }
        int prev = (base == 0) ? -1 : __ldg(segs + base - 1);
#pragma unroll
        for (int k = 0; k < PPT; k++) {
            int s = vv[k];
            if (s != prev)
                for (int q = prev + 1; q <= s; q++) g_off[q] = base + k;
            prev = s;
        }
        if (base + PPT >= P)
            for (int q = prev + 1; q <= NISEG; q++) g_off[q] = P;
    }
}

// ---------------------------------------------------------------------------
// Seg kernel: 4 warps/segment (stride-12 interleave), 3 groups x 10
// pair-lanes, MLP-4 batches, shfl + shared combine; mean + bias + sigmoid.
// Block = 256 threads = 8 warps = 2 segments.
// ---------------------------------------------------------------------------
__global__ __launch_bounds__(256)
void seg_kernel(const int* __restrict__ pidx, const float* __restrict__ bias,
                float* __restrict__ out) {
    const int t = threadIdx.x;
    const int w = t >> 5;
    const int lane = t & 31;
    const int h = w & 3;                 // quarter of segment
    const int s = blockIdx.x * 2 + (w >> 2);

    const int start = __ldg(&g_off[s]);
    const int end   = __ldg(&g_off[s + 1]);

    const int g = lane / NPAIR;          // 0..2 active; lanes 30,31 idle
    const int j = lane - g * NPAIR;

    __shared__ ull sAcc[8 * NPAIR];

    ull acc0 = 0, acc1 = 0;
    if (g < 3) {
        int p = start + 3 * h + g;       // stride 12 across 4 warps
        for (; p + 36 < end; p += 48) {
            int r0 = __ldg(pidx + p);
            int r1 = __ldg(pidx + p + 12);
            int r2 = __ldg(pidx + p + 24);
            int r3 = __ldg(pidx + p + 36);
            ull v0 = *(const ull*)&g_Z[(size_t)r0 * ZROWF + 2 * j];
            ull v1 = *(const ull*)&g_Z[(size_t)r1 * ZROWF + 2 * j];
            ull v2 = *(const ull*)&g_Z[(size_t)r2 * ZROWF + 2 * j];
            ull v3 = *(const ull*)&g_Z[(size_t)r3 * ZROWF + 2 * j];
            add2(acc0, v0); add2(acc1, v1);
            add2(acc0, v2); add2(acc1, v3);
        }
        for (; p < end; p += 12) {
            int r = __ldg(pidx + p);
            ull v = *(const ull*)&g_Z[(size_t)r * ZROWF + 2 * j];
            add2(acc0, v);
        }
        add2(acc0, acc1);
    }

    ull v1 = __shfl_down_sync(0xffffffffu, acc0, 10);
    ull v2 = __shfl_down_sync(0xffffffffu, acc0, 20);
    add2(acc0, v1);
    add2(acc0, v2);

    if (lane < NPAIR) sAcc[w * NPAIR + lane] = acc0;
    __syncthreads();

    if (h == 0 && lane < NPAIR) {
        ull total = sAcc[w * NPAIR + lane];
        add2(total, sAcc[(w + 1) * NPAIR + lane]);
        add2(total, sAcc[(w + 2) * NPAIR + lane]);
        add2(total, sAcc[(w + 3) * NPAIR + lane]);
        float f0, f1; unpack2(total, f0, f1);
        float cnt = (float)(end - start);
        float inv = 1.0f / fmaxf(cnt, 1.0f);
        int c0 = 2 * lane;
        float x0 = f0 * inv + __ldg(bias + c0);
        out[(size_t)s * NC + c0] = 1.0f / (1.0f + __expf(-x0));
        if (c0 + 1 < NC) {
            float x1 = f1 * inv + __ldg(bias + c0 + 1);
            out[(size_t)s * NC + c0 + 1] = 1.0f / (1.0f + __expf(-x1));
        }
    }
}

// ---------------------------------------------------------------------------
extern "C" void kernel_launch(void* const* d_in, const int* in_sizes, int n_in,
                              void* d_out, int out_size) {
    const float* X    = (const float*)d_in[0];
    const float* W    = (const float*)d_in[1];
    const float* b    = (const float*)d_in[2];
    const int*   pidx = (const int*)d_in[3];
    const int*   segs = (const int*)d_in[4];
    float*       out  = (float*)d_out;

    const int P = in_sizes[3];
    const int boundsBlocks = (P + THREADS * PPT - 1) / (THREADS * PPT);

    fat_kernel<<<PROJ_BLOCKS + boundsBlocks, THREADS>>>(X, W, segs, P);
    seg_kernel<<<NISEG / 2, 256>>>(pidx, b, out);
}

// round 15
// speedup vs baseline: 1.0525x; 1.0525x over previous
#include <cuda_runtime.h>

// Fixed problem shapes
#define DIMD 272
#define NC   19
#define WN   24                  // padded W cols = 3 n-tiles of 8
#define NPAIR 10
#define ZROWF 32                 // Z row stride floats = 128 B
#define NROWS 65536
#define NISEG 4096
#define THREADS 128
#define WARPS 4
#define WROWS 16                 // rows per warp
#define TB_ROWS (WARPS * WROWS)          // 64 rows per proj block
#define PROJ_BLOCKS (NROWS / TB_ROWS)    // 1024
#define NSTAGE 17                // 272 cols = 17 chunks of 16
#define XST 80                   // stage row stride bytes (64 data + 16 pad)
#define DEPTH 3
#define WSTAGE_BYTES (WROWS * XST)       // 1280 per warp per stage
#define WRING_BYTES (DEPTH * WSTAGE_BYTES)  // 3840 per warp
#define PPT 16                   // points/thread in bounds part

typedef unsigned long long ull;

__device__ float g_Z[(size_t)NROWS * ZROWF];    // 8 MB, 128B rows (fp32!)
__device__ int   g_off[NISEG + 1];

__device__ __forceinline__ void unpack2(ull v, float& lo, float& hi) {
    asm("mov.b64 {%0, %1}, %2;" : "=f"(lo), "=f"(hi) : "l"(v));
}
__device__ __forceinline__ void add2(ull& d, ull a) {
    asm("add.rn.f32x2 %0, %0, %1;" : "+l"(d) : "l"(a));
}
__device__ __forceinline__ unsigned f2tf32(float f) {
    unsigned u; asm("cvt.rna.tf32.f32 %0, %1;" : "=r"(u) : "f"(f)); return u;
}
__device__ __forceinline__ void mma_tf32(float* d, unsigned a0, unsigned a1,
                                         unsigned a2, unsigned a3,
                                         unsigned b0, unsigned b1) {
    asm volatile(
        "mma.sync.aligned.m16n8k8.row.col.f32.tf32.tf32.f32 "
        "{%0,%1,%2,%3}, {%4,%5,%6,%7}, {%8,%9}, {%0,%1,%2,%3};"
        : "+f"(d[0]), "+f"(d[1]), "+f"(d[2]), "+f"(d[3])
        : "r"(a0), "r"(a1), "r"(a2), "r"(a3), "r"(b0), "r"(b1));
}
__device__ __forceinline__ void cpasync16(unsigned smem, const void* g) {
    asm volatile("cp.async.cg.shared.global [%0], [%1], 16;"
                 :: "r"(smem), "l"(g));
}
__device__ __forceinline__ void cpcommit() {
    asm volatile("cp.async.commit_group;");
}
__device__ __forceinline__ void cpwait2() {
    asm volatile("cp.async.wait_group 2;");
}

// ---------------------------------------------------------------------------
// Fat kernel: blocks [0, PROJ_BLOCKS) compute Z = X@W with tf32 mma.sync fed
// by warp-autonomous cp.async rings (no block barriers in the mainloop).
// Remaining blocks compute segment boundary offsets.
// ---------------------------------------------------------------------------
__global__ __launch_bounds__(THREADS)
void fat_kernel(const float* __restrict__ X, const float* __restrict__ W,
                const int* __restrict__ segs, int P) {
    if (blockIdx.x < PROJ_BLOCKS) {
        __shared__ __align__(16) unsigned ws[DIMD * WN];        // 26112 B
        __shared__ __align__(16) char xs[WARPS * WRING_BYTES];  // 15360 B

        const int t = threadIdx.x;
        const int warp = t >> 5;
        const int lane = t & 31;
        const int row0 = blockIdx.x * TB_ROWS + warp * WROWS;
        const char* gX = (const char*)(X + (size_t)row0 * DIMD);
        const unsigned ring = (unsigned)__cvta_generic_to_shared(xs)
                            + (unsigned)(warp * WRING_BYTES);

        // Warp-local stage issue: 16 rows x 64 B = 64x16B chunks, 2/lane.
        // (1088 = 17*64: every 64-B chunk is 64-B aligned in gmem.)
        auto issue_stage = [&](int s) {
            unsigned sb = ring + (unsigned)((s % DEPTH) * WSTAGE_BYTES);
            const char* gbase = gX + (size_t)s * 64;
#pragma unroll
            for (int k = 0; k < 2; k++) {
                int i = lane + k * 32;          // 0..63
                int r = i >> 2;
                int c = i & 3;
                cpasync16(sb + (unsigned)(r * XST + c * 16),
                          gbase + (size_t)r * (DIMD * 4) + c * 16);
            }
        };

        issue_stage(0); cpcommit();
        issue_stage(1); cpcommit();
        issue_stage(2); cpcommit();

        // Stage W -> tf32 in shared while cp.asyncs fly
        for (int i = t; i < DIMD * WN; i += THREADS) {
            int dd = i / WN, c = i - dd * WN;
            float v = (c < NC) ? W[dd * NC + c] : 0.f;
            ws[i] = f2tf32(v);
        }
        __syncthreads();          // only block barrier: ws visible

        const int qrow = lane >> 2;           // 0..7
        const int qcol = lane & 3;            // 0..3

        float d[3][4];
#pragma unroll
        for (int n = 0; n < 3; n++)
#pragma unroll
            for (int q = 0; q < 4; q++) d[n][q] = 0.f;

        for (int s = 0; s < NSTAGE; s++) {
            cpwait2();            // this lane's stage-s copies done
            __syncwarp();         // whole warp's copies done

            const char* sbase = xs + warp * WRING_BYTES
                              + (s % DEPTH) * WSTAGE_BYTES;
            // bank = (20r + qcol + co) mod 32: all 32 lanes distinct.
            const float* ar0 = (const float*)(sbase + qrow * XST) + qcol;
            const float* ar1 = (const float*)(sbase + (qrow + 8) * XST) + qcol;

#pragma unroll
            for (int ks = 0; ks < 2; ks++) {
                const int co = ks * 8;
                unsigned a0 = f2tf32(ar0[co]);
                unsigned a1 = f2tf32(ar1[co]);
                unsigned a2 = f2tf32(ar0[co + 4]);
                unsigned a3 = f2tf32(ar1[co + 4]);

                const int kc = s * 16 + co;
                const unsigned* wb = ws + (kc + qcol) * WN + qrow;
#pragma unroll
                for (int n = 0; n < 3; n++) {
                    unsigned b0 = wb[n * 8];
                    unsigned b1 = wb[n * 8 + 4 * WN];
                    mma_tf32(d[n], a0, a1, a2, a3, b0, b1);
                }
            }

            __syncwarp();         // all lanes done reading buffer (s%DEPTH)
            if (s + 3 < NSTAGE) issue_stage(s + 3);
            cpcommit();           // unconditional: uniform group count
        }

        // Epilogue: d[n][0,1] -> row qrow cols n*8+2*qcol ; d[n][2,3] -> +8
        const int r0 = row0 + qrow;
        const int r1 = r0 + 8;
#pragma unroll
        for (int n = 0; n < 3; n++) {
            int c = n * 8 + qcol * 2;
            *(float2*)&g_Z[(size_t)r0 * ZROWF + c] =
                make_float2(d[n][0], d[n][1]);
            *(float2*)&g_Z[(size_t)r1 * ZROWF + c] =
                make_float2(d[n][2], d[n][3]);
        }
    } else {
        // ----------------- segment bounds part -----------------
        const int base = (blockIdx.x - PROJ_BLOCKS) * (THREADS * PPT)
                       + threadIdx.x * PPT;
        if (base >= P) return;
        int vv[PPT];
        const int4* s4 = (const int4*)(segs + base);
#pragma unroll
        for (int q = 0; q < PPT / 4; q++) {
            int4 v = __ldg(s4 + q);
            vv[q*4+0] = v.x; vv[q*4+1] = v.y; vv[q*4+2] = v.z; vv[q*4+3] = v.w;
        }
        int prev = (base == 0) ? -1 : __ldg(segs + base - 1);
#pragma unroll
        for (int k = 0; k < PPT; k++) {
            int s = vv[k];
            if (s != prev)
                for (int q = prev + 1; q <= s; q++) g_off[q] = base + k;
            prev = s;
        }
        if (base + PPT >= P)
            for (int q = prev + 1; q <= NISEG; q++) g_off[q] = P;
    }
}

// ---------------------------------------------------------------------------
// Seg kernel (round-8 proven): 2 warps/segment, 3 groups x 10 pair-lanes,
// MLP-4 batches, shfl + shared combine; mean + bias + sigmoid.
// ---------------------------------------------------------------------------
__global__ __launch_bounds__(256)
void seg_kernel(const int* __restrict__ pidx, const float* __restrict__ bias,
                float* __restrict__ out) {
    const int t = threadIdx.x;
    const int w = t >> 5;
    const int lane = t & 31;
    const int h = w & 1;
    const int s = blockIdx.x * 4 + (w >> 1);

    const int start = __ldg(&g_off[s]);
    const int end   = __ldg(&g_off[s + 1]);

    const int g = lane / NPAIR;          // 0..2 active; lanes 30,31 idle
    const int j = lane - g * NPAIR;

    __shared__ ull sAcc[8 * NPAIR];

    ull acc0 = 0, acc1 = 0;
    if (g < 3) {
        int p = start + 3 * h + g;       // stride 6 across both warps
        for (; p + 18 < end; p += 24) {
            int r0 = __ldg(pidx + p);
            int r1 = __ldg(pidx + p + 6);
            int r2 = __ldg(pidx + p + 12);
            int r3 = __ldg(pidx + p + 18);
            ull v0 = *(const ull*)&g_Z[(size_t)r0 * ZROWF + 2 * j];
            ull v1 = *(const ull*)&g_Z[(size_t)r1 * ZROWF + 2 * j];
            ull v2 = *(const ull*)&g_Z[(size_t)r2 * ZROWF + 2 * j];
            ull v3 = *(const ull*)&g_Z[(size_t)r3 * ZROWF + 2 * j];
            add2(acc0, v0); add2(acc1, v1);
            add2(acc0, v2); add2(acc1, v3);
        }
        for (; p < end; p += 6) {
            int r = __ldg(pidx + p);
            ull v = *(const ull*)&g_Z[(size_t)r * ZROWF + 2 * j];
            add2(acc0, v);
        }
        add2(acc0, acc1);
    }

    ull v1 = __shfl_down_sync(0xffffffffu, acc0, 10);
    ull v2 = __shfl_down_sync(0xffffffffu, acc0, 20);
    add2(acc0, v1);
    add2(acc0, v2);

    if (lane < NPAIR) sAcc[w * NPAIR + lane] = acc0;
    __syncthreads();

    if (h == 0 && lane < NPAIR) {
        ull total = sAcc[w * NPAIR + lane];
        add2(total, sAcc[(w + 1) * NPAIR + lane]);
        float f0, f1; unpack2(total, f0, f1);
        float cnt = (float)(end - start);
        float inv = 1.0f / fmaxf(cnt, 1.0f);
        int c0 = 2 * lane;
        float x0 = f0 * inv + __ldg(bias + c0);
        out[(size_t)s * NC + c0] = 1.0f / (1.0f + __expf(-x0));
        if (c0 + 1 < NC) {
            float x1 = f1 * inv + __ldg(bias + c0 + 1);
            out[(size_t)s * NC + c0 + 1] = 1.0f / (1.0f + __expf(-x1));
        }
    }
}

// ---------------------------------------------------------------------------
extern "C" void kernel_launch(void* const* d_in, const int* in_sizes, int n_in,
                              void* d_out, int out_size) {
    const float* X    = (const float*)d_in[0];
    const float* W    = (const float*)d_in[1];
    const float* b    = (const float*)d_in[2];
    const int*   pidx = (const int*)d_in[3];
    const int*   segs = (const int*)d_in[4];
    float*       out  = (float*)d_out;

    const int P = in_sizes[3];
    const int boundsBlocks = (P + THREADS * PPT - 1) / (THREADS * PPT);

    fat_kernel<<<PROJ_BLOCKS + boundsBlocks, THREADS>>>(X, W, segs, P);
    seg_kernel<<<NISEG / 4, 256>>>(pidx, b, out);
}